// round 5
// baseline (speedup 1.0000x reference)
#include <cuda_runtime.h>
#include <cuda_bf16.h>
#include <stdint.h>

#define B_  2
#define T_  2048
#define S_  2048
#define E_  1024
#define H_  16
#define D_  64
#define BT  (B_*T_)
#define Z_  (B_*H_)
#define SCALE 0.125f

typedef __nv_bfloat16 bf16;

// Scratch (__device__ globals; allocation-free rule)
__device__ bf16 g_Th[(size_t)BT*E_], g_Tl[(size_t)BT*E_];   // tgt hi/lo
__device__ bf16 g_Sh[(size_t)BT*E_], g_Sl[(size_t)BT*E_];   // src hi/lo
__device__ bf16 g_Wqh[(size_t)E_*E_], g_Wql[(size_t)E_*E_];
__device__ bf16 g_Wkh[(size_t)E_*E_], g_Wkl[(size_t)E_*E_];
__device__ bf16 g_Wvh[(size_t)E_*E_], g_Wvl[(size_t)E_*E_];
__device__ bf16 g_Woh[(size_t)E_*E_], g_Wol[(size_t)E_*E_];
__device__ bf16 g_Qh[(size_t)Z_*T_*D_], g_Ql[(size_t)Z_*T_*D_];
__device__ bf16 g_Kh[(size_t)Z_*S_*D_], g_Kl[(size_t)Z_*S_*D_];
__device__ bf16 g_Vh[(size_t)Z_*S_*D_], g_Vl[(size_t)Z_*S_*D_];
__device__ bf16 g_Ch[(size_t)BT*E_], g_Cl[(size_t)BT*E_];
__device__ float g_rs[(size_t)Z_*T_];

__device__ __forceinline__ void cvt_hilo2(float x0, float x1, uint32_t& h, uint32_t& l) {
    asm("cvt.rn.bf16x2.f32 %0, %1, %2;" : "=r"(h) : "f"(x1), "f"(x0));
    float h0 = __uint_as_float(h << 16);
    float h1 = __uint_as_float(h & 0xffff0000u);
    asm("cvt.rn.bf16x2.f32 %0, %1, %2;" : "=r"(l) : "f"(x1 - h1), "f"(x0 - h0));
}

__device__ __forceinline__ void mma16816(float c[4], const uint32_t a[4], const uint32_t b[2]) {
    asm volatile("mma.sync.aligned.m16n8k16.row.col.f32.bf16.bf16.f32 "
        "{%0,%1,%2,%3}, {%4,%5,%6,%7}, {%8,%9}, {%0,%1,%2,%3};"
        : "+f"(c[0]), "+f"(c[1]), "+f"(c[2]), "+f"(c[3])
        : "r"(a[0]), "r"(a[1]), "r"(a[2]), "r"(a[3]), "r"(b[0]), "r"(b[1]));
}

__device__ __forceinline__ void cpa16(const void* smem, const void* g) {
    uint32_t s = (uint32_t)__cvta_generic_to_shared(smem);
    asm volatile("cp.async.cg.shared.global [%0], [%1], 16;" :: "r"(s), "l"(g));
}
__device__ __forceinline__ void cp_commit() { asm volatile("cp.async.commit_group;"); }
template<int N> __device__ __forceinline__ void cp_wait() {
    asm volatile("cp.async.wait_group %0;" :: "n"(N));
}

// exp on the FMA pipe (2^t, deg-6, magic rounding). rel err ~2e-7.
__device__ __forceinline__ float fast_exp(float x) {
    const float MAGIC = 12582912.0f;
    float t = x * 1.44269504088896f;
    float r = t + MAGIC;
    int ib = __float_as_int(r);
    float f = t - (r - MAGIC);
    float p = 1.54035304e-4f;
    p = fmaf(p, f, 1.33335581e-3f);
    p = fmaf(p, f, 9.61812911e-3f);
    p = fmaf(p, f, 5.55041087e-2f);
    p = fmaf(p, f, 2.40226507e-1f);
    p = fmaf(p, f, 6.93147182e-1f);
    p = fmaf(p, f, 1.0f);
    return p * __int_as_float((ib + 127) << 23);
}

// ---------------------------------------------------------------------------
// Pre-convert fp32 -> bf16 hi/lo (vectorized, n4 = elems/4)
// ---------------------------------------------------------------------------
__global__ void k_cvt(const float* __restrict__ in, bf16* __restrict__ oh,
                      bf16* __restrict__ ol, int n4)
{
    int i = blockIdx.x * blockDim.x + threadIdx.x;
    if (i >= n4) return;
    float4 v = ((const float4*)in)[i];
    uint32_t h01, l01, h23, l23;
    cvt_hilo2(v.x, v.y, h01, l01);
    cvt_hilo2(v.z, v.w, h23, l23);
    ((uint2*)oh)[i] = make_uint2(h01, h23);
    ((uint2*)ol)[i] = make_uint2(l01, l23);
}

// ---------------------------------------------------------------------------
// Pure-bf16 NT GEMM 128x128x32, cp.async double-buffered, bf16x3 accumulate.
// TO_HL=true: write bf16 hi/lo head-major Q/K/V. false: fp32 C + bias.
// ---------------------------------------------------------------------------
#define PLD 40                       // bf16 row stride (80B), conflict-free
#define PSZ (128*PLD)                // elems per array per buffer

template<bool TO_HL>
__global__ __launch_bounds__(256) void k_projb(
    const bf16* __restrict__ Agh, const bf16* __restrict__ Agl,
    const bf16* __restrict__ Bgh, const bf16* __restrict__ Bgl,
    float* __restrict__ C, const float* __restrict__ bias,
    bf16* __restrict__ Oh, bf16* __restrict__ Ol)
{
    extern __shared__ bf16 sm[];
    bf16* Ah = sm;                 // [2][PSZ]
    bf16* Al = sm + 2 * PSZ;
    bf16* Bh = sm + 4 * PSZ;
    bf16* Bl = sm + 6 * PSZ;

    const int tid = threadIdx.x, lane = tid & 31, wid = tid >> 5;
    const int wm = wid >> 2, wn = wid & 3;
    const int bm = blockIdx.y * 128, bn = blockIdx.x * 128;
    const int rr = lane >> 2, q2 = (lane & 3) << 1;

    const int cr = tid >> 2;             // 0..63? no: 256 threads, 2 chunks each
    // chunk map: j = tid + i*256, r=j>>2, c=(j&3)*8

    auto issue = [&](int t, int buf) {
        const size_t k0 = (size_t)t * 32;
        #pragma unroll
        for (int i = 0; i < 2; i++) {
            int j = tid + i * 256;
            int r = j >> 2, c = (j & 3) << 3;
            size_t ga = (size_t)(bm + r) * E_ + k0 + c;
            size_t gb = (size_t)(bn + r) * E_ + k0 + c;
            int so = buf * PSZ + r * PLD + c;
            cpa16(&Ah[so], &Agh[ga]);
            cpa16(&Al[so], &Agl[ga]);
            cpa16(&Bh[so], &Bgh[gb]);
            cpa16(&Bl[so], &Bgl[gb]);
        }
        cp_commit();
    };

    float acc[4][4][4] = {};

    issue(0, 0);
    for (int t = 0; t < 32; t++) {
        const int buf = t & 1;
        if (t < 31) { issue(t + 1, buf ^ 1); cp_wait<1>(); }
        else cp_wait<0>();
        __syncthreads();

        const bf16* Ahb = Ah + buf * PSZ;
        const bf16* Alb = Al + buf * PSZ;
        const bf16* Bhb = Bh + buf * PSZ;
        const bf16* Blb = Bl + buf * PSZ;

        #pragma unroll
        for (int ks = 0; ks < 2; ks++) {
            const int kq = ks * 16 + q2;
            uint32_t bh[4][2], bl[4][2];
            #pragma unroll
            for (int nt = 0; nt < 4; nt++) {
                int n = wn * 32 + nt * 8 + rr;
                bh[nt][0] = *(const uint32_t*)&Bhb[n * PLD + kq];
                bh[nt][1] = *(const uint32_t*)&Bhb[n * PLD + kq + 8];
                bl[nt][0] = *(const uint32_t*)&Blb[n * PLD + kq];
                bl[nt][1] = *(const uint32_t*)&Blb[n * PLD + kq + 8];
            }
            #pragma unroll
            for (int mt = 0; mt < 4; mt++) {
                int m = wm * 64 + mt * 16 + rr;
                uint32_t ah[4], al[4];
                ah[0] = *(const uint32_t*)&Ahb[m * PLD + kq];
                ah[1] = *(const uint32_t*)&Ahb[(m + 8) * PLD + kq];
                ah[2] = *(const uint32_t*)&Ahb[m * PLD + kq + 8];
                ah[3] = *(const uint32_t*)&Ahb[(m + 8) * PLD + kq + 8];
                al[0] = *(const uint32_t*)&Alb[m * PLD + kq];
                al[1] = *(const uint32_t*)&Alb[(m + 8) * PLD + kq];
                al[2] = *(const uint32_t*)&Alb[m * PLD + kq + 8];
                al[3] = *(const uint32_t*)&Alb[(m + 8) * PLD + kq + 8];
                #pragma unroll
                for (int nt = 0; nt < 4; nt++) {
                    mma16816(acc[mt][nt], ah, bh[nt]);
                    mma16816(acc[mt][nt], al, bh[nt]);
                    mma16816(acc[mt][nt], ah, bl[nt]);
                }
            }
        }
        __syncthreads();
    }

    #pragma unroll
    for (int mt = 0; mt < 4; mt++) {
        #pragma unroll
        for (int nt = 0; nt < 4; nt++) {
            int n = bn + wn * 32 + nt * 8 + q2;
            #pragma unroll
            for (int rh = 0; rh < 2; rh++) {
                int m = bm + wm * 64 + mt * 16 + rr + rh * 8;
                float v0 = acc[mt][nt][rh * 2 + 0];
                float v1 = acc[mt][nt][rh * 2 + 1];
                if (TO_HL) {
                    int b = m >> 11, t = m & 2047;
                    int h = n >> 6, d = n & 63;
                    size_t off = ((size_t)(b * H_ + h) * T_ + t) * D_ + d;
                    uint32_t hh, ll;
                    cvt_hilo2(v0, v1, hh, ll);
                    *(uint32_t*)&Oh[off] = hh;
                    *(uint32_t*)&Ol[off] = ll;
                } else {
                    float* p = C + (size_t)m * E_ + n;
                    p[0] = v0 + bias[n];
                    p[1] = v1 + bias[n + 1];
                }
            }
        }
    }
}

// ---------------------------------------------------------------------------
// Fused scores + exp, cp.async double-buffered K tiles.
// ---------------------------------------------------------------------------
#define LDQ 72
#define QSZ (128*LDQ)

__global__ __launch_bounds__(256) void k_sco(float* __restrict__ attn)
{
    extern __shared__ bf16 sm[];
    bf16* Qh = sm;
    bf16* Ql = sm + QSZ;
    bf16* Kh = sm + 2 * QSZ;      // [2][QSZ]
    bf16* Kl = sm + 4 * QSZ;
    __shared__ float rs[128];

    const int tid = threadIdx.x, lane = tid & 31, wid = tid >> 5;
    const int wm = wid >> 1, wn = wid & 1;
    const int rr = lane >> 2, q2 = (lane & 3) << 1;
    const int z = blockIdx.y, t0 = blockIdx.x * 128;

    const bf16* Qhg = g_Qh + ((size_t)z * T_ + t0) * D_;
    const bf16* Qlg = g_Ql + ((size_t)z * T_ + t0) * D_;
    const bf16* Khg = g_Kh + (size_t)z * S_ * D_;
    const bf16* Klg = g_Kl + (size_t)z * S_ * D_;
    float* Ab = attn + (size_t)z * T_ * S_;

    if (tid < 128) rs[tid] = 0.f;

    #pragma unroll
    for (int i = 0; i < 4; i++) {
        int idx = tid + i * 256;
        int r = idx >> 3, c = (idx & 7) << 3;
        *(uint4*)&Qh[r * LDQ + c] = *(const uint4*)&Qhg[r * D_ + c];
        *(uint4*)&Ql[r * LDQ + c] = *(const uint4*)&Qlg[r * D_ + c];
    }

    auto issueK = [&](int si, int buf) {
        const bf16* Kt = Khg + (size_t)si * 128 * D_;
        const bf16* Lt = Klg + (size_t)si * 128 * D_;
        #pragma unroll
        for (int i = 0; i < 4; i++) {
            int j = tid + i * 256;
            int r = j >> 3, c = (j & 7) << 3;
            cpa16(&Kh[buf * QSZ + r * LDQ + c], &Kt[r * D_ + c]);
            cpa16(&Kl[buf * QSZ + r * LDQ + c], &Lt[r * D_ + c]);
        }
        cp_commit();
    };

    float psum[2][2] = {};
    issueK(0, 0);

    for (int si = 0; si < 16; si++) {
        const int buf = si & 1;
        if (si < 15) { issueK(si + 1, buf ^ 1); cp_wait<1>(); }
        else cp_wait<0>();
        __syncthreads();

        const bf16* Khb = Kh + buf * QSZ;
        const bf16* Klb = Kl + buf * QSZ;

        float acc[2][8][4] = {};
        #pragma unroll
        for (int ks = 0; ks < 4; ks++) {
            const int kq = ks * 16 + q2;
            uint32_t ah[2][4], al[2][4];
            #pragma unroll
            for (int mt = 0; mt < 2; mt++) {
                int m = wm * 32 + mt * 16 + rr;
                ah[mt][0] = *(const uint32_t*)&Qh[m * LDQ + kq];
                ah[mt][1] = *(const uint32_t*)&Qh[(m + 8) * LDQ + kq];
                ah[mt][2] = *(const uint32_t*)&Qh[m * LDQ + kq + 8];
                ah[mt][3] = *(const uint32_t*)&Qh[(m + 8) * LDQ + kq + 8];
                al[mt][0] = *(const uint32_t*)&Ql[m * LDQ + kq];
                al[mt][1] = *(const uint32_t*)&Ql[(m + 8) * LDQ + kq];
                al[mt][2] = *(const uint32_t*)&Ql[m * LDQ + kq + 8];
                al[mt][3] = *(const uint32_t*)&Ql[(m + 8) * LDQ + kq + 8];
            }
            #pragma unroll
            for (int nt = 0; nt < 8; nt++) {
                int n = wn * 64 + nt * 8 + rr;
                uint32_t bh[2] = { *(const uint32_t*)&Khb[n * LDQ + kq],
                                   *(const uint32_t*)&Khb[n * LDQ + kq + 8] };
                uint32_t bl[2] = { *(const uint32_t*)&Klb[n * LDQ + kq],
                                   *(const uint32_t*)&Klb[n * LDQ + kq + 8] };
                #pragma unroll
                for (int mt = 0; mt < 2; mt++) {
                    mma16816(acc[mt][nt], ah[mt], bh);
                    mma16816(acc[mt][nt], al[mt], bh);
                    mma16816(acc[mt][nt], ah[mt], bl);
                }
            }
        }

        #pragma unroll
        for (int mt = 0; mt < 2; mt++) {
            int r0 = t0 + wm * 32 + mt * 16 + rr;
            #pragma unroll
            for (int nt = 0; nt < 8; nt++) {
                int n0 = si * 128 + wn * 64 + nt * 8 + q2;
                float e0 = fast_exp(acc[mt][nt][0] * SCALE);
                float e1 = fast_exp(acc[mt][nt][1] * SCALE);
                float e2 = fast_exp(acc[mt][nt][2] * SCALE);
                float e3 = fast_exp(acc[mt][nt][3] * SCALE);
                psum[mt][0] += e0 + e1;
                psum[mt][1] += e2 + e3;
                *(float2*)&Ab[(size_t)r0 * S_ + n0]       = make_float2(e0, e1);
                *(float2*)&Ab[(size_t)(r0 + 8) * S_ + n0] = make_float2(e2, e3);
            }
        }
        __syncthreads();
    }

    #pragma unroll
    for (int mt = 0; mt < 2; mt++) {
        atomicAdd(&rs[wm * 32 + mt * 16 + rr], psum[mt][0]);
        atomicAdd(&rs[wm * 32 + mt * 16 + rr + 8], psum[mt][1]);
    }
    __syncthreads();
    if (tid < 128) g_rs[(size_t)z * T_ + t0 + tid] = rs[tid];
}

// ---------------------------------------------------------------------------
// Fused normalize + ctx, BK=64. Writes final attn in-place; ctx as bf16 hi/lo.
// ---------------------------------------------------------------------------
__global__ __launch_bounds__(256) void k_ctx(float* __restrict__ attn)
{
    extern __shared__ bf16 sm[];
    bf16* Ph = sm;                  // 128 x 72
    bf16* Pl = sm + 128 * LDQ;
    bf16* Vh = sm + 2 * 128 * LDQ;  // 64 x 72
    bf16* Vl = sm + 2 * 128 * LDQ + 64 * LDQ;
    __shared__ float inv_s[128];

    const int tid = threadIdx.x, lane = tid & 31, wid = tid >> 5;
    const int wm = wid >> 1, wn = wid & 1;
    const int rr = lane >> 2, q2 = (lane & 3) << 1;
    const int z = blockIdx.y, t0 = blockIdx.x * 128;
    const int b = z >> 4, h = z & 15;

    float* Ab = attn + ((size_t)z * T_ + t0) * S_;
    const bf16* Vhg = g_Vh + (size_t)z * S_ * D_;
    const bf16* Vlg = g_Vl + (size_t)z * S_ * D_;

    if (tid < 128) inv_s[tid] = 1.0f / g_rs[(size_t)z * T_ + t0 + tid];
    __syncthreads();

    float acc[2][4][4] = {};

    for (int k0 = 0; k0 < S_; k0 += 64) {
        // V tile 64(s) x 64(d) -> smem transposed [d][s]
        #pragma unroll
        for (int i = 0; i < 8; i++) {
            int j = tid + i * 256;
            int d2 = j & 31, k = j >> 5;       // k: 0..63
            uint32_t vh = *(const uint32_t*)&Vhg[(size_t)(k0 + k) * D_ + 2 * d2];
            uint32_t vl = *(const uint32_t*)&Vlg[(size_t)(k0 + k) * D_ + 2 * d2];
            Vh[(2 * d2) * LDQ + k]     = __ushort_as_bfloat16((unsigned short)(vh & 0xffff));
            Vh[(2 * d2 + 1) * LDQ + k] = __ushort_as_bfloat16((unsigned short)(vh >> 16));
            Vl[(2 * d2) * LDQ + k]     = __ushort_as_bfloat16((unsigned short)(vl & 0xffff));
            Vl[(2 * d2 + 1) * LDQ + k] = __ushort_as_bfloat16((unsigned short)(vl >> 16));
        }
        // P tile 128x64: read e, normalize, write final attn, split hi/lo
        #pragma unroll
        for (int i = 0; i < 8; i++) {
            int idx = tid + i * 256;
            int r = idx >> 4, c = (idx & 15) << 2;
            float4 e4 = *(float4*)&Ab[(size_t)r * S_ + k0 + c];
            float inv = inv_s[r];
            e4.x *= inv; e4.y *= inv; e4.z *= inv; e4.w *= inv;
            *(float4*)&Ab[(size_t)r * S_ + k0 + c] = e4;
            uint32_t h01, l01, h23, l23;
            cvt_hilo2(e4.x, e4.y, h01, l01);
            cvt_hilo2(e4.z, e4.w, h23, l23);
            *(uint2*)&Ph[r * LDQ + c] = make_uint2(h01, h23);
            *(uint2*)&Pl[r * LDQ + c] = make_uint2(l01, l23);
        }
        __syncthreads();

        #pragma unroll
        for (int ks = 0; ks < 4; ks++) {
            const int kq = ks * 16 + q2;
            uint32_t ah[2][4], al[2][4];
            #pragma unroll
            for (int mt = 0; mt < 2; mt++) {
                int m = wm * 32 + mt * 16 + rr;
                ah[mt][0] = *(const uint32_t*)&Ph[m * LDQ + kq];
                ah[mt][1] = *(const uint32_t*)&Ph[(m + 8) * LDQ + kq];
                ah[mt][2] = *(const uint32_t*)&Ph[m * LDQ + kq + 8];
                ah[mt][3] = *(const uint32_t*)&Ph[(m + 8) * LDQ + kq + 8];
                al[mt][0] = *(const uint32_t*)&Pl[m * LDQ + kq];
                al[mt][1] = *(const uint32_t*)&Pl[(m + 8) * LDQ + kq];
                al[mt][2] = *(const uint32_t*)&Pl[m * LDQ + kq + 8];
                al[mt][3] = *(const uint32_t*)&Pl[(m + 8) * LDQ + kq + 8];
            }
            #pragma unroll
            for (int nt = 0; nt < 4; nt++) {
                int n = wn * 32 + nt * 8 + rr;
                uint32_t bh[2] = { *(const uint32_t*)&Vh[n * LDQ + kq],
                                   *(const uint32_t*)&Vh[n * LDQ + kq + 8] };
                uint32_t bl[2] = { *(const uint32_t*)&Vl[n * LDQ + kq],
                                   *(const uint32_t*)&Vl[n * LDQ + kq + 8] };
                #pragma unroll
                for (int mt = 0; mt < 2; mt++) {
                    mma16816(acc[mt][nt], ah[mt], bh);
                    mma16816(acc[mt][nt], al[mt], bh);
                    mma16816(acc[mt][nt], ah[mt], bl);
                }
            }
        }
        __syncthreads();
    }

    // epilogue: ctx as bf16 hi/lo for the final projection
    #pragma unroll
    for (int mt = 0; mt < 2; mt++) {
        #pragma unroll
        for (int nt = 0; nt < 4; nt++) {
            int d = wn * 32 + nt * 8 + q2;
            #pragma unroll
            for (int rh = 0; rh < 2; rh++) {
                int m = t0 + wm * 32 + mt * 16 + rr + rh * 8;
                size_t off = ((size_t)(b * T_ + m)) * E_ + h * D_ + d;
                uint32_t hh, ll;
                cvt_hilo2(acc[mt][nt][rh * 2], acc[mt][nt][rh * 2 + 1], hh, ll);
                *(uint32_t*)&g_Ch[off] = hh;
                *(uint32_t*)&g_Cl[off] = ll;
            }
        }
    }
}

// ---------------------------------------------------------------------------
extern "C" void kernel_launch(void* const* d_in, const int* in_sizes, int n_in,
                              void* d_out, int out_size)
{
    const float* src = (const float*)d_in[0];
    const float* tgt = (const float*)d_in[1];
    const float* Wq  = (const float*)d_in[2];
    const float* Wk  = (const float*)d_in[3];
    const float* Wv  = (const float*)d_in[4];
    const float* Wo  = (const float*)d_in[5];
    const float* bo  = (const float*)d_in[6];

    float* out  = (float*)d_out;
    float* attn = out + (size_t)BT * E_;

    bf16 *Th, *Tl, *Sh, *Sl, *Wqh, *Wql, *Wkh, *Wkl, *Wvh, *Wvl, *Woh, *Wol;
    bf16 *Qh, *Ql, *Kh, *Kl, *Vh, *Vl, *Ch, *Cl;
    cudaGetSymbolAddress((void**)&Th, g_Th);   cudaGetSymbolAddress((void**)&Tl, g_Tl);
    cudaGetSymbolAddress((void**)&Sh, g_Sh);   cudaGetSymbolAddress((void**)&Sl, g_Sl);
    cudaGetSymbolAddress((void**)&Wqh, g_Wqh); cudaGetSymbolAddress((void**)&Wql, g_Wql);
    cudaGetSymbolAddress((void**)&Wkh, g_Wkh); cudaGetSymbolAddress((void**)&Wkl, g_Wkl);
    cudaGetSymbolAddress((void**)&Wvh, g_Wvh); cudaGetSymbolAddress((void**)&Wvl, g_Wvl);
    cudaGetSymbolAddress((void**)&Woh, g_Woh); cudaGetSymbolAddress((void**)&Wol, g_Wol);
    cudaGetSymbolAddress((void**)&Qh, g_Qh);   cudaGetSymbolAddress((void**)&Ql, g_Ql);
    cudaGetSymbolAddress((void**)&Kh, g_Kh);   cudaGetSymbolAddress((void**)&Kl, g_Kl);
    cudaGetSymbolAddress((void**)&Vh, g_Vh);   cudaGetSymbolAddress((void**)&Vl, g_Vl);
    cudaGetSymbolAddress((void**)&Ch, g_Ch);   cudaGetSymbolAddress((void**)&Cl, g_Cl);

    const int projSmem = 8 * PSZ * (int)sizeof(bf16);       // 81920
    const int scoSmem  = 6 * QSZ * (int)sizeof(bf16);       // 110592
    const int ctxSmem  = (2 * 128 + 2 * 64) * LDQ * (int)sizeof(bf16);

    static bool attr_set = false;
    if (!attr_set) {
        cudaFuncSetAttribute(k_projb<true>,  cudaFuncAttributeMaxDynamicSharedMemorySize, projSmem);
        cudaFuncSetAttribute(k_projb<false>, cudaFuncAttributeMaxDynamicSharedMemorySize, projSmem);
        cudaFuncSetAttribute(k_sco, cudaFuncAttributeMaxDynamicSharedMemorySize, scoSmem);
        cudaFuncSetAttribute(k_ctx, cudaFuncAttributeMaxDynamicSharedMemorySize, ctxSmem);
        attr_set = true;
    }

    dim3 blk(256);

    // convert everything once
    k_cvt<<<(BT * E_ / 4 + 255) / 256, 256>>>(tgt, Th, Tl, BT * E_ / 4);
    k_cvt<<<(BT * E_ / 4 + 255) / 256, 256>>>(src, Sh, Sl, BT * E_ / 4);
    k_cvt<<<(E_ * E_ / 4 + 255) / 256, 256>>>(Wq, Wqh, Wql, E_ * E_ / 4);
    k_cvt<<<(E_ * E_ / 4 + 255) / 256, 256>>>(Wk, Wkh, Wkl, E_ * E_ / 4);
    k_cvt<<<(E_ * E_ / 4 + 255) / 256, 256>>>(Wv, Wvh, Wvl, E_ * E_ / 4);
    k_cvt<<<(E_ * E_ / 4 + 255) / 256, 256>>>(Wo, Woh, Wol, E_ * E_ / 4);

    dim3 gproj(E_ / 128, BT / 128);
    k_projb<true><<<gproj, blk, projSmem>>>(Th, Tl, Wqh, Wql, nullptr, nullptr, Qh, Ql);
    k_projb<true><<<gproj, blk, projSmem>>>(Sh, Sl, Wkh, Wkl, nullptr, nullptr, Kh, Kl);
    k_projb<true><<<gproj, blk, projSmem>>>(Sh, Sl, Wvh, Wvl, nullptr, nullptr, Vh, Vl);

    k_sco<<<dim3(T_ / 128, Z_), blk, scoSmem>>>(attn);

    k_ctx<<<dim3(T_ / 128, Z_), blk, ctxSmem>>>(attn);

    k_projb<false><<<gproj, blk, projSmem>>>(Ch, Cl, Woh, Wol, out, bo, nullptr, nullptr);
}

// round 7
// speedup vs baseline: 1.0726x; 1.0726x over previous
#include <cuda_runtime.h>
#include <cuda_bf16.h>
#include <stdint.h>

#define B_  2
#define T_  2048
#define S_  2048
#define E_  1024
#define H_  16
#define D_  64
#define BT  (B_*T_)
#define Z_  (B_*H_)
#define SCALE 0.125f

typedef __nv_bfloat16 bf16;

// Scratch (__device__ globals; allocation-free rule)
__device__ bf16 g_Th[(size_t)BT*E_], g_Tl[(size_t)BT*E_];
__device__ bf16 g_Sh[(size_t)BT*E_], g_Sl[(size_t)BT*E_];
__device__ bf16 g_Wqh[(size_t)E_*E_], g_Wql[(size_t)E_*E_];
__device__ bf16 g_Wkh[(size_t)E_*E_], g_Wkl[(size_t)E_*E_];
__device__ bf16 g_Wvh[(size_t)E_*E_], g_Wvl[(size_t)E_*E_];
__device__ bf16 g_Woh[(size_t)E_*E_], g_Wol[(size_t)E_*E_];
__device__ bf16 g_Qh[(size_t)Z_*T_*D_], g_Ql[(size_t)Z_*T_*D_];
__device__ bf16 g_Kh[(size_t)Z_*S_*D_], g_Kl[(size_t)Z_*S_*D_];
__device__ bf16 g_Vh[(size_t)Z_*S_*D_], g_Vl[(size_t)Z_*S_*D_];
__device__ bf16 g_Ch[(size_t)BT*E_], g_Cl[(size_t)BT*E_];
__device__ float g_rs[(size_t)Z_*T_];

__device__ __forceinline__ uint32_t smem_u32(const void* p) {
    return (uint32_t)__cvta_generic_to_shared(p);
}
__device__ __forceinline__ void cvt_hilo2(float x0, float x1, uint32_t& h, uint32_t& l) {
    asm("cvt.rn.bf16x2.f32 %0, %1, %2;" : "=r"(h) : "f"(x1), "f"(x0));
    float h0 = __uint_as_float(h << 16);
    float h1 = __uint_as_float(h & 0xffff0000u);
    asm("cvt.rn.bf16x2.f32 %0, %1, %2;" : "=r"(l) : "f"(x1 - h1), "f"(x0 - h0));
}
__device__ __forceinline__ void mma16816(float c[4], const uint32_t a[4], const uint32_t b[2]) {
    asm volatile("mma.sync.aligned.m16n8k16.row.col.f32.bf16.bf16.f32 "
        "{%0,%1,%2,%3}, {%4,%5,%6,%7}, {%8,%9}, {%0,%1,%2,%3};"
        : "+f"(c[0]), "+f"(c[1]), "+f"(c[2]), "+f"(c[3])
        : "r"(a[0]), "r"(a[1]), "r"(a[2]), "r"(a[3]), "r"(b[0]), "r"(b[1]));
}
// ldmatrix x4: 4 8x8 b16 matrices, lane groups of 8 provide row addrs
__device__ __forceinline__ void ldsm4(uint32_t r[4], uint32_t a) {
    asm volatile("ldmatrix.sync.aligned.m8n8.x4.shared.b16 {%0,%1,%2,%3}, [%4];"
        : "=r"(r[0]), "=r"(r[1]), "=r"(r[2]), "=r"(r[3]) : "r"(a));
}
__device__ __forceinline__ void cpa16(uint32_t s, const void* g) {
    asm volatile("cp.async.cg.shared.global [%0], [%1], 16;" :: "r"(s), "l"(g));
}
__device__ __forceinline__ void cpa16p(const void* smem, const void* g) {
    cpa16(smem_u32(smem), g);
}
__device__ __forceinline__ void cp_commit() { asm volatile("cp.async.commit_group;"); }
template<int N> __device__ __forceinline__ void cp_wait() {
    asm volatile("cp.async.wait_group %0;" :: "n"(N));
}
__device__ __forceinline__ float fast_exp(float x) {
    const float MAGIC = 12582912.0f;
    float t = x * 1.44269504088896f;
    float r = t + MAGIC;
    int ib = __float_as_int(r);
    float f = t - (r - MAGIC);
    float p = 1.54035304e-4f;
    p = fmaf(p, f, 1.33335581e-3f);
    p = fmaf(p, f, 9.61812911e-3f);
    p = fmaf(p, f, 5.55041087e-2f);
    p = fmaf(p, f, 2.40226507e-1f);
    p = fmaf(p, f, 6.93147182e-1f);
    p = fmaf(p, f, 1.0f);
    return p * __int_as_float((ib + 127) << 23);
}

// ---------------------------------------------------------------------------
__global__ void k_cvt(const float* __restrict__ in, bf16* __restrict__ oh,
                      bf16* __restrict__ ol, int n4)
{
    int i = blockIdx.x * blockDim.x + threadIdx.x;
    if (i >= n4) return;
    float4 v = ((const float4*)in)[i];
    uint32_t h01, l01, h23, l23;
    cvt_hilo2(v.x, v.y, h01, l01);
    cvt_hilo2(v.z, v.w, h23, l23);
    ((uint2*)oh)[i] = make_uint2(h01, h23);
    ((uint2*)ol)[i] = make_uint2(l01, l23);
}

// ---------------------------------------------------------------------------
// Pure-bf16 NT GEMM 128x128x32, cp.async 2-stage, ldmatrix fragments, bf16x3.
// ---------------------------------------------------------------------------
#define PLD 40
#define PSZ (128*PLD)

template<bool TO_HL>
__global__ __launch_bounds__(256) void k_projb(
    const bf16* __restrict__ Agh, const bf16* __restrict__ Agl,
    const bf16* __restrict__ Bgh, const bf16* __restrict__ Bgl,
    float* __restrict__ C, const float* __restrict__ bias,
    bf16* __restrict__ Oh, bf16* __restrict__ Ol)
{
    extern __shared__ bf16 sm[];
    bf16* Ah = sm;
    bf16* Al = sm + 2 * PSZ;
    bf16* Bh = sm + 4 * PSZ;
    bf16* Bl = sm + 6 * PSZ;

    const int tid = threadIdx.x, lane = tid & 31, wid = tid >> 5;
    const int wm = wid >> 2, wn = wid & 3;
    const int bm = blockIdx.y * 128, bn = blockIdx.x * 128;
    const int rr = lane >> 2, q2 = (lane & 3) << 1;

    // ldmatrix lane address components
    const int lrow = lane & 15, lkof = (lane >> 4) << 3;               // A
    const int brow = ((lane >> 4) << 3) + (lane & 7);
    const int bkof = ((lane >> 3) & 1) << 3;                           // B

    auto issue = [&](int t, int buf) {
        const size_t k0 = (size_t)t * 32;
        #pragma unroll
        for (int i = 0; i < 2; i++) {
            int j = tid + i * 256;
            int r = j >> 2, c = (j & 3) << 3;
            size_t ga = (size_t)(bm + r) * E_ + k0 + c;
            size_t gb = (size_t)(bn + r) * E_ + k0 + c;
            int so = buf * PSZ + r * PLD + c;
            cpa16p(&Ah[so], &Agh[ga]);
            cpa16p(&Al[so], &Agl[ga]);
            cpa16p(&Bh[so], &Bgh[gb]);
            cpa16p(&Bl[so], &Bgl[gb]);
        }
        cp_commit();
    };

    float acc[4][4][4] = {};

    issue(0, 0);
    for (int t = 0; t < 32; t++) {
        const int buf = t & 1;
        if (t < 31) { issue(t + 1, buf ^ 1); cp_wait<1>(); }
        else cp_wait<0>();
        __syncthreads();

        const int bofs = buf * PSZ;
        uint32_t aAh[4], aAl[4];
        #pragma unroll
        for (int mt = 0; mt < 4; mt++) {
            int m = wm * 64 + mt * 16 + lrow;
            aAh[mt] = smem_u32(&Ah[bofs + m * PLD + lkof]);
            aAl[mt] = smem_u32(&Al[bofs + m * PLD + lkof]);
        }
        uint32_t aBh[2], aBl[2];
        #pragma unroll
        for (int ng = 0; ng < 2; ng++) {
            int n = wn * 32 + ng * 16 + brow;
            aBh[ng] = smem_u32(&Bh[bofs + n * PLD + bkof]);
            aBl[ng] = smem_u32(&Bl[bofs + n * PLD + bkof]);
        }

        #pragma unroll
        for (int ks = 0; ks < 2; ks++) {
            const uint32_t kb = ks * 32;         // bytes (16 bf16)
            uint32_t bh4[2][4], bl4[2][4];
            #pragma unroll
            for (int ng = 0; ng < 2; ng++) {
                ldsm4(bh4[ng], aBh[ng] + kb);
                ldsm4(bl4[ng], aBl[ng] + kb);
            }
            #pragma unroll
            for (int mt = 0; mt < 4; mt++) {
                uint32_t ah[4], al[4];
                ldsm4(ah, aAh[mt] + kb);
                ldsm4(al, aAl[mt] + kb);
                #pragma unroll
                for (int nt = 0; nt < 4; nt++) {
                    const int ng = nt >> 1, s = (nt & 1) << 1;
                    uint32_t bh[2] = { bh4[ng][s], bh4[ng][s + 1] };
                    uint32_t bl[2] = { bl4[ng][s], bl4[ng][s + 1] };
                    mma16816(acc[mt][nt], ah, bh);
                    mma16816(acc[mt][nt], al, bh);
                    mma16816(acc[mt][nt], ah, bl);
                }
            }
        }
        __syncthreads();
    }

    #pragma unroll
    for (int mt = 0; mt < 4; mt++) {
        #pragma unroll
        for (int nt = 0; nt < 4; nt++) {
            int n = bn + wn * 32 + nt * 8 + q2;
            #pragma unroll
            for (int rh = 0; rh < 2; rh++) {
                int m = bm + wm * 64 + mt * 16 + rr + rh * 8;
                float v0 = acc[mt][nt][rh * 2 + 0];
                float v1 = acc[mt][nt][rh * 2 + 1];
                if (TO_HL) {
                    int b = m >> 11, t = m & 2047;
                    int h = n >> 6, d = n & 63;
                    size_t off = ((size_t)(b * H_ + h) * T_ + t) * D_ + d;
                    uint32_t hh, ll;
                    cvt_hilo2(v0, v1, hh, ll);
                    *(uint32_t*)&Oh[off] = hh;
                    *(uint32_t*)&Ol[off] = ll;
                } else {
                    float* p = C + (size_t)m * E_ + n;
                    p[0] = v0 + bias[n];
                    p[1] = v1 + bias[n + 1];
                }
            }
        }
    }
}

// ---------------------------------------------------------------------------
// Fused scores + exp, cp.async 2-stage K tiles, ldmatrix fragments.
// ---------------------------------------------------------------------------
#define LDQ 72
#define QSZ (128*LDQ)

__global__ __launch_bounds__(256) void k_sco(float* __restrict__ attn)
{
    extern __shared__ bf16 sm[];
    bf16* Qh = sm;
    bf16* Ql = sm + QSZ;
    bf16* Kh = sm + 2 * QSZ;
    bf16* Kl = sm + 4 * QSZ;
    __shared__ float rs[128];

    const int tid = threadIdx.x, lane = tid & 31, wid = tid >> 5;
    const int wm = wid >> 1, wn = wid & 1;
    const int rr = lane >> 2, q2 = (lane & 3) << 1;
    const int z = blockIdx.y, t0 = blockIdx.x * 128;

    const int lrow = lane & 15, lkof = (lane >> 4) << 3;
    const int brow = ((lane >> 4) << 3) + (lane & 7);
    const int bkof = ((lane >> 3) & 1) << 3;

    const bf16* Qhg = g_Qh + ((size_t)z * T_ + t0) * D_;
    const bf16* Qlg = g_Ql + ((size_t)z * T_ + t0) * D_;
    const bf16* Khg = g_Kh + (size_t)z * S_ * D_;
    const bf16* Klg = g_Kl + (size_t)z * S_ * D_;
    float* Ab = attn + (size_t)z * T_ * S_;

    if (tid < 128) rs[tid] = 0.f;

    #pragma unroll
    for (int i = 0; i < 4; i++) {
        int idx = tid + i * 256;
        int r = idx >> 3, c = (idx & 7) << 3;
        *(uint4*)&Qh[r * LDQ + c] = *(const uint4*)&Qhg[r * D_ + c];
        *(uint4*)&Ql[r * LDQ + c] = *(const uint4*)&Qlg[r * D_ + c];
    }

    auto issueK = [&](int si, int buf) {
        const bf16* Kt = Khg + (size_t)si * 128 * D_;
        const bf16* Lt = Klg + (size_t)si * 128 * D_;
        #pragma unroll
        for (int i = 0; i < 4; i++) {
            int j = tid + i * 256;
            int r = j >> 3, c = (j & 7) << 3;
            cpa16p(&Kh[buf * QSZ + r * LDQ + c], &Kt[r * D_ + c]);
            cpa16p(&Kl[buf * QSZ + r * LDQ + c], &Lt[r * D_ + c]);
        }
        cp_commit();
    };

    // Q fragment addresses (fixed across si)
    uint32_t aQh[2], aQl[2];
    #pragma unroll
    for (int mt = 0; mt < 2; mt++) {
        int m = wm * 32 + mt * 16 + lrow;
        aQh[mt] = smem_u32(&Qh[m * LDQ + lkof]);
        aQl[mt] = smem_u32(&Ql[m * LDQ + lkof]);
    }

    float psum[2][2] = {};
    issueK(0, 0);

    for (int si = 0; si < 16; si++) {
        const int buf = si & 1;
        if (si < 15) { issueK(si + 1, buf ^ 1); cp_wait<1>(); }
        else cp_wait<0>();
        __syncthreads();

        const int kofs = buf * QSZ;
        uint32_t aKh[4], aKl[4];
        #pragma unroll
        for (int ng = 0; ng < 4; ng++) {
            int n = wn * 64 + ng * 16 + brow;
            aKh[ng] = smem_u32(&Kh[kofs + n * LDQ + bkof]);
            aKl[ng] = smem_u32(&Kl[kofs + n * LDQ + bkof]);
        }

        float acc[2][8][4] = {};
        #pragma unroll
        for (int ks = 0; ks < 4; ks++) {
            const uint32_t kb = ks * 32;
            uint32_t ah[2][4], al[2][4];
            #pragma unroll
            for (int mt = 0; mt < 2; mt++) {
                ldsm4(ah[mt], aQh[mt] + kb);
                ldsm4(al[mt], aQl[mt] + kb);
            }
            #pragma unroll
            for (int ng = 0; ng < 4; ng++) {
                uint32_t bh4[4], bl4[4];
                ldsm4(bh4, aKh[ng] + kb);
                ldsm4(bl4, aKl[ng] + kb);
                #pragma unroll
                for (int s = 0; s < 2; s++) {
                    const int nt = ng * 2 + s;
                    uint32_t bh[2] = { bh4[2 * s], bh4[2 * s + 1] };
                    uint32_t bl[2] = { bl4[2 * s], bl4[2 * s + 1] };
                    #pragma unroll
                    for (int mt = 0; mt < 2; mt++) {
                        mma16816(acc[mt][nt], ah[mt], bh);
                        mma16816(acc[mt][nt], al[mt], bh);
                        mma16816(acc[mt][nt], ah[mt], bl);
                    }
                }
            }
        }

        #pragma unroll
        for (int mt = 0; mt < 2; mt++) {
            int r0 = t0 + wm * 32 + mt * 16 + rr;
            #pragma unroll
            for (int nt = 0; nt < 8; nt++) {
                int n0 = si * 128 + wn * 64 + nt * 8 + q2;
                float e0 = fast_exp(acc[mt][nt][0] * SCALE);
                float e1 = fast_exp(acc[mt][nt][1] * SCALE);
                float e2 = fast_exp(acc[mt][nt][2] * SCALE);
                float e3 = fast_exp(acc[mt][nt][3] * SCALE);
                psum[mt][0] += e0 + e1;
                psum[mt][1] += e2 + e3;
                *(float2*)&Ab[(size_t)r0 * S_ + n0]       = make_float2(e0, e1);
                *(float2*)&Ab[(size_t)(r0 + 8) * S_ + n0] = make_float2(e2, e3);
            }
        }
        __syncthreads();
    }

    #pragma unroll
    for (int mt = 0; mt < 2; mt++) {
        atomicAdd(&rs[wm * 32 + mt * 16 + rr], psum[mt][0]);
        atomicAdd(&rs[wm * 32 + mt * 16 + rr + 8], psum[mt][1]);
    }
    __syncthreads();
    if (tid < 128) g_rs[(size_t)z * T_ + t0 + tid] = rs[tid];
}

// ---------------------------------------------------------------------------
// Fused normalize + ctx, BK=64, ldmatrix fragments. ctx as bf16 hi/lo.
// ---------------------------------------------------------------------------
__global__ __launch_bounds__(256) void k_ctx(float* __restrict__ attn)
{
    extern __shared__ bf16 sm[];
    bf16* Ph = sm;
    bf16* Pl = sm + 128 * LDQ;
    bf16* Vh = sm + 2 * 128 * LDQ;
    bf16* Vl = sm + 2 * 128 * LDQ + 64 * LDQ;
    __shared__ float inv_s[128];

    const int tid = threadIdx.x, lane = tid & 31, wid = tid >> 5;
    const int wm = wid >> 1, wn = wid & 1;
    const int rr = lane >> 2, q2 = (lane & 3) << 1;
    const int z = blockIdx.y, t0 = blockIdx.x * 128;
    const int b = z >> 4, h = z & 15;

    const int lrow = lane & 15, lkof = (lane >> 4) << 3;
    const int brow = ((lane >> 4) << 3) + (lane & 7);
    const int bkof = ((lane >> 3) & 1) << 3;

    float* Ab = attn + ((size_t)z * T_ + t0) * S_;
    const bf16* Vhg = g_Vh + (size_t)z * S_ * D_;
    const bf16* Vlg = g_Vl + (size_t)z * S_ * D_;

    if (tid < 128) inv_s[tid] = 1.0f / g_rs[(size_t)z * T_ + t0 + tid];
    __syncthreads();

    // fragment addresses (fixed buffers)
    uint32_t aPh[2], aPl[2], aVh[2], aVl[2];
    #pragma unroll
    for (int mt = 0; mt < 2; mt++) {
        int m = wm * 32 + mt * 16 + lrow;
        aPh[mt] = smem_u32(&Ph[m * LDQ + lkof]);
        aPl[mt] = smem_u32(&Pl[m * LDQ + lkof]);
    }
    #pragma unroll
    for (int ng = 0; ng < 2; ng++) {
        int n = wn * 32 + ng * 16 + brow;
        aVh[ng] = smem_u32(&Vh[n * LDQ + bkof]);
        aVl[ng] = smem_u32(&Vl[n * LDQ + bkof]);
    }

    float acc[2][4][4] = {};

    for (int k0 = 0; k0 < S_; k0 += 64) {
        #pragma unroll
        for (int i = 0; i < 8; i++) {
            int j = tid + i * 256;
            int d2 = j & 31, k = j >> 5;
            uint32_t vh = *(const uint32_t*)&Vhg[(size_t)(k0 + k) * D_ + 2 * d2];
            uint32_t vl = *(const uint32_t*)&Vlg[(size_t)(k0 + k) * D_ + 2 * d2];
            Vh[(2 * d2) * LDQ + k]     = __ushort_as_bfloat16((unsigned short)(vh & 0xffff));
            Vh[(2 * d2 + 1) * LDQ + k] = __ushort_as_bfloat16((unsigned short)(vh >> 16));
            Vl[(2 * d2) * LDQ + k]     = __ushort_as_bfloat16((unsigned short)(vl & 0xffff));
            Vl[(2 * d2 + 1) * LDQ + k] = __ushort_as_bfloat16((unsigned short)(vl >> 16));
        }
        #pragma unroll
        for (int i = 0; i < 8; i++) {
            int idx = tid + i * 256;
            int r = idx >> 4, c = (idx & 15) << 2;
            float4 e4 = *(float4*)&Ab[(size_t)r * S_ + k0 + c];
            float inv = inv_s[r];
            e4.x *= inv; e4.y *= inv; e4.z *= inv; e4.w *= inv;
            *(float4*)&Ab[(size_t)r * S_ + k0 + c] = e4;
            uint32_t h01, l01, h23, l23;
            cvt_hilo2(e4.x, e4.y, h01, l01);
            cvt_hilo2(e4.z, e4.w, h23, l23);
            *(uint2*)&Ph[r * LDQ + c] = make_uint2(h01, h23);
            *(uint2*)&Pl[r * LDQ + c] = make_uint2(l01, l23);
        }
        __syncthreads();

        #pragma unroll
        for (int ks = 0; ks < 4; ks++) {
            const uint32_t kb = ks * 32;
            uint32_t ah[2][4], al[2][4];
            #pragma unroll
            for (int mt = 0; mt < 2; mt++) {
                ldsm4(ah[mt], aPh[mt] + kb);
                ldsm4(al[mt], aPl[mt] + kb);
            }
            #pragma unroll
            for (int ng = 0; ng < 2; ng++) {
                uint32_t bh4[4], bl4[4];
                ldsm4(bh4, aVh[ng] + kb);
                ldsm4(bl4, aVl[ng] + kb);
                #pragma unroll
                for (int s = 0; s < 2; s++) {
                    const int nt = ng * 2 + s;
                    uint32_t bh[2] = { bh4[2 * s], bh4[2 * s + 1] };
                    uint32_t bl[2] = { bl4[2 * s], bl4[2 * s + 1] };
                    #pragma unroll
                    for (int mt = 0; mt < 2; mt++) {
                        mma16816(acc[mt][nt], ah[mt], bh);
                        mma16816(acc[mt][nt], al[mt], bh);
                        mma16816(acc[mt][nt], ah[mt], bl);
                    }
                }
            }
        }
        __syncthreads();
    }

    #pragma unroll
    for (int mt = 0; mt < 2; mt++) {
        #pragma unroll
        for (int nt = 0; nt < 4; nt++) {
            int d = wn * 32 + nt * 8 + q2;
            #pragma unroll
            for (int rh = 0; rh < 2; rh++) {
                int mr = t0 + wm * 32 + mt * 16 + rr + rh * 8;
                size_t off = ((size_t)(b * T_ + mr)) * E_ + h * D_ + d;
                uint32_t hh, ll;
                cvt_hilo2(acc[mt][nt][rh * 2], acc[mt][nt][rh * 2 + 1], hh, ll);
                *(uint32_t*)&g_Ch[off] = hh;
                *(uint32_t*)&g_Cl[off] = ll;
            }
        }
    }
}

// ---------------------------------------------------------------------------
extern "C" void kernel_launch(void* const* d_in, const int* in_sizes, int n_in,
                              void* d_out, int out_size)
{
    const float* src = (const float*)d_in[0];
    const float* tgt = (const float*)d_in[1];
    const float* Wq  = (const float*)d_in[2];
    const float* Wk  = (const float*)d_in[3];
    const float* Wv  = (const float*)d_in[4];
    const float* Wo  = (const float*)d_in[5];
    const float* bo  = (const float*)d_in[6];

    float* out  = (float*)d_out;
    float* attn = out + (size_t)BT * E_;

    bf16 *Th, *Tl, *Sh, *Sl, *Wqh, *Wql, *Wkh, *Wkl, *Wvh, *Wvl, *Woh, *Wol;
    bf16 *Qh, *Ql, *Kh, *Kl, *Vh, *Vl, *Ch, *Cl;
    cudaGetSymbolAddress((void**)&Th, g_Th);   cudaGetSymbolAddress((void**)&Tl, g_Tl);
    cudaGetSymbolAddress((void**)&Sh, g_Sh);   cudaGetSymbolAddress((void**)&Sl, g_Sl);
    cudaGetSymbolAddress((void**)&Wqh, g_Wqh); cudaGetSymbolAddress((void**)&Wql, g_Wql);
    cudaGetSymbolAddress((void**)&Wkh, g_Wkh); cudaGetSymbolAddress((void**)&Wkl, g_Wkl);
    cudaGetSymbolAddress((void**)&Wvh, g_Wvh); cudaGetSymbolAddress((void**)&Wvl, g_Wvl);
    cudaGetSymbolAddress((void**)&Woh, g_Woh); cudaGetSymbolAddress((void**)&Wol, g_Wol);
    cudaGetSymbolAddress((void**)&Qh, g_Qh);   cudaGetSymbolAddress((void**)&Ql, g_Ql);
    cudaGetSymbolAddress((void**)&Kh, g_Kh);   cudaGetSymbolAddress((void**)&Kl, g_Kl);
    cudaGetSymbolAddress((void**)&Vh, g_Vh);   cudaGetSymbolAddress((void**)&Vl, g_Vl);
    cudaGetSymbolAddress((void**)&Ch, g_Ch);   cudaGetSymbolAddress((void**)&Cl, g_Cl);

    const int projSmem = 8 * PSZ * (int)sizeof(bf16);
    const int scoSmem  = 6 * QSZ * (int)sizeof(bf16);
    const int ctxSmem  = (2 * 128 + 2 * 64) * LDQ * (int)sizeof(bf16);

    static bool attr_set = false;
    if (!attr_set) {
        cudaFuncSetAttribute(k_projb<true>,  cudaFuncAttributeMaxDynamicSharedMemorySize, projSmem);
        cudaFuncSetAttribute(k_projb<false>, cudaFuncAttributeMaxDynamicSharedMemorySize, projSmem);
        cudaFuncSetAttribute(k_sco, cudaFuncAttributeMaxDynamicSharedMemorySize, scoSmem);
        cudaFuncSetAttribute(k_ctx, cudaFuncAttributeMaxDynamicSharedMemorySize, ctxSmem);
        attr_set = true;
    }

    dim3 blk(256);

    k_cvt<<<(BT * E_ / 4 + 255) / 256, 256>>>(tgt, Th, Tl, BT * E_ / 4);
    k_cvt<<<(BT * E_ / 4 + 255) / 256, 256>>>(src, Sh, Sl, BT * E_ / 4);
    k_cvt<<<(E_ * E_ / 4 + 255) / 256, 256>>>(Wq, Wqh, Wql, E_ * E_ / 4);
    k_cvt<<<(E_ * E_ / 4 + 255) / 256, 256>>>(Wk, Wkh, Wkl, E_ * E_ / 4);
    k_cvt<<<(E_ * E_ / 4 + 255) / 256, 256>>>(Wv, Wvh, Wvl, E_ * E_ / 4);
    k_cvt<<<(E_ * E_ / 4 + 255) / 256, 256>>>(Wo, Woh, Wol, E_ * E_ / 4);

    dim3 gproj(E_ / 128, BT / 128);
    k_projb<true><<<gproj, blk, projSmem>>>(Th, Tl, Wqh, Wql, nullptr, nullptr, Qh, Ql);
    k_projb<true><<<gproj, blk, projSmem>>>(Sh, Sl, Wkh, Wkl, nullptr, nullptr, Kh, Kl);
    k_projb<true><<<gproj, blk, projSmem>>>(Sh, Sl, Wvh, Wvl, nullptr, nullptr, Vh, Vl);

    k_sco<<<dim3(T_ / 128, Z_), blk, scoSmem>>>(attn);

    k_ctx<<<dim3(T_ / 128, Z_), blk, ctxSmem>>>(attn);

    k_projb<false><<<gproj, blk, projSmem>>>(Ch, Cl, Woh, Wol, out, bo, nullptr, nullptr);
}

// round 8
// speedup vs baseline: 1.1458x; 1.0683x over previous
#include <cuda_runtime.h>
#include <cuda_bf16.h>
#include <stdint.h>

#define B_  2
#define T_  2048
#define S_  2048
#define E_  1024
#define H_  16
#define D_  64
#define BT  (B_*T_)
#define Z_  (B_*H_)
#define SCALE 0.125f

typedef __nv_bfloat16 bf16;

// Scratch (__device__ globals; allocation-free rule)
__device__ bf16 g_Th[(size_t)BT*E_], g_Tl[(size_t)BT*E_];
__device__ bf16 g_Sh[(size_t)BT*E_], g_Sl[(size_t)BT*E_];
__device__ bf16 g_Wqh[(size_t)E_*E_], g_Wql[(size_t)E_*E_];
__device__ bf16 g_Wkh[(size_t)E_*E_], g_Wkl[(size_t)E_*E_];
__device__ bf16 g_Wvh[(size_t)E_*E_], g_Wvl[(size_t)E_*E_];
__device__ bf16 g_Woh[(size_t)E_*E_], g_Wol[(size_t)E_*E_];
__device__ bf16 g_Qh[(size_t)Z_*T_*D_], g_Ql[(size_t)Z_*T_*D_];
__device__ bf16 g_Kh[(size_t)Z_*S_*D_], g_Kl[(size_t)Z_*S_*D_];
__device__ bf16 g_Vh[(size_t)Z_*S_*D_], g_Vl[(size_t)Z_*S_*D_];
__device__ bf16 g_Ch[(size_t)BT*E_], g_Cl[(size_t)BT*E_];
__device__ float g_rs[(size_t)Z_*T_];

__device__ __forceinline__ uint32_t smem_u32(const void* p) {
    return (uint32_t)__cvta_generic_to_shared(p);
}
__device__ __forceinline__ void cvt_hilo2(float x0, float x1, uint32_t& h, uint32_t& l) {
    asm("cvt.rn.bf16x2.f32 %0, %1, %2;" : "=r"(h) : "f"(x1), "f"(x0));
    float h0 = __uint_as_float(h << 16);
    float h1 = __uint_as_float(h & 0xffff0000u);
    asm("cvt.rn.bf16x2.f32 %0, %1, %2;" : "=r"(l) : "f"(x1 - h1), "f"(x0 - h0));
}
__device__ __forceinline__ void mma16816(float c[4], const uint32_t a[4], const uint32_t b[2]) {
    asm volatile("mma.sync.aligned.m16n8k16.row.col.f32.bf16.bf16.f32 "
        "{%0,%1,%2,%3}, {%4,%5,%6,%7}, {%8,%9}, {%0,%1,%2,%3};"
        : "+f"(c[0]), "+f"(c[1]), "+f"(c[2]), "+f"(c[3])
        : "r"(a[0]), "r"(a[1]), "r"(a[2]), "r"(a[3]), "r"(b[0]), "r"(b[1]));
}
__device__ __forceinline__ void ldsm4(uint32_t r[4], uint32_t a) {
    asm volatile("ldmatrix.sync.aligned.m8n8.x4.shared.b16 {%0,%1,%2,%3}, [%4];"
        : "=r"(r[0]), "=r"(r[1]), "=r"(r[2]), "=r"(r[3]) : "r"(a));
}
__device__ __forceinline__ void ldsm4t(uint32_t r[4], uint32_t a) {
    asm volatile("ldmatrix.sync.aligned.m8n8.x4.trans.shared.b16 {%0,%1,%2,%3}, [%4];"
        : "=r"(r[0]), "=r"(r[1]), "=r"(r[2]), "=r"(r[3]) : "r"(a));
}
__device__ __forceinline__ void cpa16(uint32_t s, const void* g) {
    asm volatile("cp.async.cg.shared.global [%0], [%1], 16;" :: "r"(s), "l"(g));
}
__device__ __forceinline__ void cpa16p(const void* smem, const void* g) {
    cpa16(smem_u32(smem), g);
}
__device__ __forceinline__ void cp_commit() { asm volatile("cp.async.commit_group;"); }
template<int N> __device__ __forceinline__ void cp_wait() {
    asm volatile("cp.async.wait_group %0;" :: "n"(N));
}
// deg-4 exp on FMA pipe; rel err ~5e-5 (softmax-normalized downstream)
__device__ __forceinline__ float fast_exp(float x) {
    const float MAGIC = 12582912.0f;
    float t = x * 1.44269504088896f;
    float r = t + MAGIC;
    int ib = __float_as_int(r);
    float f = t - (r - MAGIC);
    float p = 9.6181291e-3f;
    p = fmaf(p, f, 5.5504109e-2f);
    p = fmaf(p, f, 2.4022651e-1f);
    p = fmaf(p, f, 6.9314718e-1f);
    p = fmaf(p, f, 1.0f);
    return p * __int_as_float((ib + 127) << 23);
}

// ---------------------------------------------------------------------------
__global__ void k_cvt(const float* __restrict__ in, bf16* __restrict__ oh,
                      bf16* __restrict__ ol, int n4)
{
    int i = blockIdx.x * blockDim.x + threadIdx.x;
    if (i >= n4) return;
    float4 v = ((const float4*)in)[i];
    uint32_t h01, l01, h23, l23;
    cvt_hilo2(v.x, v.y, h01, l01);
    cvt_hilo2(v.z, v.w, h23, l23);
    ((uint2*)oh)[i] = make_uint2(h01, h23);
    ((uint2*)ol)[i] = make_uint2(l01, l23);
}

// ---------------------------------------------------------------------------
// GEMM core (NT, 128x128x32, cp.async 2-stage, ldmatrix, bf16x3)
// ---------------------------------------------------------------------------
#define PLD 40
#define PSZ (128*PLD)

template<bool TO_HL>
__device__ __forceinline__ void proj_core(
    const bf16* __restrict__ Agh, const bf16* __restrict__ Agl,
    const bf16* __restrict__ Bgh, const bf16* __restrict__ Bgl,
    float* __restrict__ C, const float* __restrict__ bias,
    bf16* __restrict__ Oh, bf16* __restrict__ Ol)
{
    extern __shared__ bf16 sm[];
    bf16* Ah = sm;
    bf16* Al = sm + 2 * PSZ;
    bf16* Bh = sm + 4 * PSZ;
    bf16* Bl = sm + 6 * PSZ;

    const int tid = threadIdx.x, lane = tid & 31, wid = tid >> 5;
    const int wm = wid >> 2, wn = wid & 3;
    const int bm = blockIdx.y * 128, bn = blockIdx.x * 128;
    const int rr = lane >> 2, q2 = (lane & 3) << 1;

    const int lrow = lane & 15, lkof = (lane >> 4) << 3;
    const int brow = ((lane >> 4) << 3) + (lane & 7);
    const int bkof = ((lane >> 3) & 1) << 3;

    auto issue = [&](int t, int buf) {
        const size_t k0 = (size_t)t * 32;
        #pragma unroll
        for (int i = 0; i < 2; i++) {
            int j = tid + i * 256;
            int r = j >> 2, c = (j & 3) << 3;
            size_t ga = (size_t)(bm + r) * E_ + k0 + c;
            size_t gb = (size_t)(bn + r) * E_ + k0 + c;
            int so = buf * PSZ + r * PLD + c;
            cpa16p(&Ah[so], &Agh[ga]);
            cpa16p(&Al[so], &Agl[ga]);
            cpa16p(&Bh[so], &Bgh[gb]);
            cpa16p(&Bl[so], &Bgl[gb]);
        }
        cp_commit();
    };

    float acc[4][4][4] = {};

    issue(0, 0);
    for (int t = 0; t < 32; t++) {
        const int buf = t & 1;
        if (t < 31) { issue(t + 1, buf ^ 1); cp_wait<1>(); }
        else cp_wait<0>();
        __syncthreads();

        const int bofs = buf * PSZ;
        uint32_t aAh[4], aAl[4];
        #pragma unroll
        for (int mt = 0; mt < 4; mt++) {
            int m = wm * 64 + mt * 16 + lrow;
            aAh[mt] = smem_u32(&Ah[bofs + m * PLD + lkof]);
            aAl[mt] = smem_u32(&Al[bofs + m * PLD + lkof]);
        }
        uint32_t aBh[2], aBl[2];
        #pragma unroll
        for (int ng = 0; ng < 2; ng++) {
            int n = wn * 32 + ng * 16 + brow;
            aBh[ng] = smem_u32(&Bh[bofs + n * PLD + bkof]);
            aBl[ng] = smem_u32(&Bl[bofs + n * PLD + bkof]);
        }

        #pragma unroll
        for (int ks = 0; ks < 2; ks++) {
            const uint32_t kb = ks * 32;
            uint32_t bh4[2][4], bl4[2][4];
            #pragma unroll
            for (int ng = 0; ng < 2; ng++) {
                ldsm4(bh4[ng], aBh[ng] + kb);
                ldsm4(bl4[ng], aBl[ng] + kb);
            }
            #pragma unroll
            for (int mt = 0; mt < 4; mt++) {
                uint32_t ah[4], al[4];
                ldsm4(ah, aAh[mt] + kb);
                ldsm4(al, aAl[mt] + kb);
                #pragma unroll
                for (int nt = 0; nt < 4; nt++) {
                    const int ng = nt >> 1, s = (nt & 1) << 1;
                    uint32_t bh[2] = { bh4[ng][s], bh4[ng][s + 1] };
                    uint32_t bl[2] = { bl4[ng][s], bl4[ng][s + 1] };
                    mma16816(acc[mt][nt], ah, bh);
                    mma16816(acc[mt][nt], al, bh);
                    mma16816(acc[mt][nt], ah, bl);
                }
            }
        }
        __syncthreads();
    }

    #pragma unroll
    for (int mt = 0; mt < 4; mt++) {
        #pragma unroll
        for (int nt = 0; nt < 4; nt++) {
            int n = bn + wn * 32 + nt * 8 + q2;
            #pragma unroll
            for (int rh = 0; rh < 2; rh++) {
                int m = bm + wm * 64 + mt * 16 + rr + rh * 8;
                float v0 = acc[mt][nt][rh * 2 + 0];
                float v1 = acc[mt][nt][rh * 2 + 1];
                if (TO_HL) {
                    int b = m >> 11, t = m & 2047;
                    int h = n >> 6, d = n & 63;
                    size_t off = ((size_t)(b * H_ + h) * T_ + t) * D_ + d;
                    uint32_t hh, ll;
                    cvt_hilo2(v0, v1, hh, ll);
                    *(uint32_t*)&Oh[off] = hh;
                    *(uint32_t*)&Ol[off] = ll;
                } else {
                    float* p = C + (size_t)m * E_ + n;
                    p[0] = v0 + bias[n];
                    p[1] = v1 + bias[n + 1];
                }
            }
        }
    }
}

// merged QKV projections: z = 0/1/2 -> Q/K/V
__global__ __launch_bounds__(256, 2) void k_proj3(
    const bf16* __restrict__ Th, const bf16* __restrict__ Tl,
    const bf16* __restrict__ Sh, const bf16* __restrict__ Sl,
    const bf16* __restrict__ Wqh, const bf16* __restrict__ Wql,
    const bf16* __restrict__ Wkh, const bf16* __restrict__ Wkl,
    const bf16* __restrict__ Wvh, const bf16* __restrict__ Wvl,
    bf16* __restrict__ Qh, bf16* __restrict__ Ql,
    bf16* __restrict__ Kh, bf16* __restrict__ Kl,
    bf16* __restrict__ Vh, bf16* __restrict__ Vl)
{
    const int z = blockIdx.z;
    const bf16* Agh = (z == 0) ? Th : Sh;
    const bf16* Agl = (z == 0) ? Tl : Sl;
    const bf16* Bgh = (z == 0) ? Wqh : (z == 1) ? Wkh : Wvh;
    const bf16* Bgl = (z == 0) ? Wql : (z == 1) ? Wkl : Wvl;
    bf16* Oh = (z == 0) ? Qh : (z == 1) ? Kh : Vh;
    bf16* Ol = (z == 0) ? Ql : (z == 1) ? Kl : Vl;
    proj_core<true>(Agh, Agl, Bgh, Bgl, nullptr, nullptr, Oh, Ol);
}

__global__ __launch_bounds__(256, 2) void k_projo(
    const bf16* __restrict__ Agh, const bf16* __restrict__ Agl,
    const bf16* __restrict__ Bgh, const bf16* __restrict__ Bgl,
    float* __restrict__ C, const float* __restrict__ bias)
{
    proj_core<false>(Agh, Agl, Bgh, Bgl, C, bias, nullptr, nullptr);
}

// ---------------------------------------------------------------------------
// Fused scores + exp, cp.async 2-stage K tiles, ldmatrix fragments.
// ---------------------------------------------------------------------------
#define LDQ 72
#define QSZ (128*LDQ)

__global__ __launch_bounds__(256, 2) void k_sco(float* __restrict__ attn)
{
    extern __shared__ bf16 sm[];
    bf16* Qh = sm;
    bf16* Ql = sm + QSZ;
    bf16* Kh = sm + 2 * QSZ;
    bf16* Kl = sm + 4 * QSZ;
    __shared__ float rs[128];

    const int tid = threadIdx.x, lane = tid & 31, wid = tid >> 5;
    const int wm = wid >> 1, wn = wid & 1;
    const int rr = lane >> 2, q2 = (lane & 3) << 1;
    const int z = blockIdx.y, t0 = blockIdx.x * 128;

    const int lrow = lane & 15, lkof = (lane >> 4) << 3;
    const int brow = ((lane >> 4) << 3) + (lane & 7);
    const int bkof = ((lane >> 3) & 1) << 3;

    const bf16* Qhg = g_Qh + ((size_t)z * T_ + t0) * D_;
    const bf16* Qlg = g_Ql + ((size_t)z * T_ + t0) * D_;
    const bf16* Khg = g_Kh + (size_t)z * S_ * D_;
    const bf16* Klg = g_Kl + (size_t)z * S_ * D_;
    float* Ab = attn + (size_t)z * T_ * S_;

    if (tid < 128) rs[tid] = 0.f;

    #pragma unroll
    for (int i = 0; i < 4; i++) {
        int idx = tid + i * 256;
        int r = idx >> 3, c = (idx & 7) << 3;
        *(uint4*)&Qh[r * LDQ + c] = *(const uint4*)&Qhg[r * D_ + c];
        *(uint4*)&Ql[r * LDQ + c] = *(const uint4*)&Qlg[r * D_ + c];
    }

    auto issueK = [&](int si, int buf) {
        const bf16* Kt = Khg + (size_t)si * 128 * D_;
        const bf16* Lt = Klg + (size_t)si * 128 * D_;
        #pragma unroll
        for (int i = 0; i < 4; i++) {
            int j = tid + i * 256;
            int r = j >> 3, c = (j & 7) << 3;
            cpa16p(&Kh[buf * QSZ + r * LDQ + c], &Kt[r * D_ + c]);
            cpa16p(&Kl[buf * QSZ + r * LDQ + c], &Lt[r * D_ + c]);
        }
        cp_commit();
    };

    uint32_t aQh[2], aQl[2];
    #pragma unroll
    for (int mt = 0; mt < 2; mt++) {
        int m = wm * 32 + mt * 16 + lrow;
        aQh[mt] = smem_u32(&Qh[m * LDQ + lkof]);
        aQl[mt] = smem_u32(&Ql[m * LDQ + lkof]);
    }

    float psum[2][2] = {};
    issueK(0, 0);

    for (int si = 0; si < 16; si++) {
        const int buf = si & 1;
        if (si < 15) { issueK(si + 1, buf ^ 1); cp_wait<1>(); }
        else cp_wait<0>();
        __syncthreads();

        const int kofs = buf * QSZ;
        uint32_t aKh[4], aKl[4];
        #pragma unroll
        for (int ng = 0; ng < 4; ng++) {
            int n = wn * 64 + ng * 16 + brow;
            aKh[ng] = smem_u32(&Kh[kofs + n * LDQ + bkof]);
            aKl[ng] = smem_u32(&Kl[kofs + n * LDQ + bkof]);
        }

        float acc[2][8][4] = {};
        #pragma unroll
        for (int ks = 0; ks < 4; ks++) {
            const uint32_t kb = ks * 32;
            uint32_t ah[2][4], al[2][4];
            #pragma unroll
            for (int mt = 0; mt < 2; mt++) {
                ldsm4(ah[mt], aQh[mt] + kb);
                ldsm4(al[mt], aQl[mt] + kb);
            }
            #pragma unroll
            for (int ng = 0; ng < 4; ng++) {
                uint32_t bh4[4], bl4[4];
                ldsm4(bh4, aKh[ng] + kb);
                ldsm4(bl4, aKl[ng] + kb);
                #pragma unroll
                for (int s = 0; s < 2; s++) {
                    const int nt = ng * 2 + s;
                    uint32_t bh[2] = { bh4[2 * s], bh4[2 * s + 1] };
                    uint32_t bl[2] = { bl4[2 * s], bl4[2 * s + 1] };
                    #pragma unroll
                    for (int mt = 0; mt < 2; mt++) {
                        mma16816(acc[mt][nt], ah[mt], bh);
                        mma16816(acc[mt][nt], al[mt], bh);
                        mma16816(acc[mt][nt], ah[mt], bl);
                    }
                }
            }
        }

        #pragma unroll
        for (int mt = 0; mt < 2; mt++) {
            int r0 = t0 + wm * 32 + mt * 16 + rr;
            #pragma unroll
            for (int nt = 0; nt < 8; nt++) {
                int n0 = si * 128 + wn * 64 + nt * 8 + q2;
                float e0 = fast_exp(acc[mt][nt][0] * SCALE);
                float e1 = fast_exp(acc[mt][nt][1] * SCALE);
                float e2 = fast_exp(acc[mt][nt][2] * SCALE);
                float e3 = fast_exp(acc[mt][nt][3] * SCALE);
                psum[mt][0] += e0 + e1;
                psum[mt][1] += e2 + e3;
                *(float2*)&Ab[(size_t)r0 * S_ + n0]       = make_float2(e0, e1);
                *(float2*)&Ab[(size_t)(r0 + 8) * S_ + n0] = make_float2(e2, e3);
            }
        }
        __syncthreads();
    }

    #pragma unroll
    for (int mt = 0; mt < 2; mt++) {
        atomicAdd(&rs[wm * 32 + mt * 16 + rr], psum[mt][0]);
        atomicAdd(&rs[wm * 32 + mt * 16 + rr + 8], psum[mt][1]);
    }
    __syncthreads();
    if (tid < 128) g_rs[(size_t)z * T_ + t0 + tid] = rs[tid];
}

// ---------------------------------------------------------------------------
// Fused normalize + ctx: cp.async double-buffered V (row-major, ldmatrix.trans)
// P normalized in-place -> final attn; PV via bf16x3; ctx as bf16 hi/lo.
// ---------------------------------------------------------------------------
#define VSZ (64*LDQ)

__global__ __launch_bounds__(256, 2) void k_ctx(float* __restrict__ attn)
{
    extern __shared__ bf16 sm[];
    bf16* Ph = sm;                       // 128 x LDQ
    bf16* Pl = sm + 128 * LDQ;
    bf16* Vh = sm + 2 * 128 * LDQ;       // [2][64 x LDQ]  row-major [s][d]
    bf16* Vl = sm + 2 * 128 * LDQ + 2 * VSZ;
    __shared__ float inv_s[128];

    const int tid = threadIdx.x, lane = tid & 31, wid = tid >> 5;
    const int wm = wid >> 1, wn = wid & 1;
    const int rr = lane >> 2, q2 = (lane & 3) << 1;
    const int z = blockIdx.y, t0 = blockIdx.x * 128;
    const int b = z >> 4, h = z & 15;

    const int lrow = lane & 15, lkof = (lane >> 4) << 3;
    // ldmatrix.trans addressing for V[s][d]: k-row + n-col-group
    const int vkrow = ((lane >> 3) & 1) * 8 + (lane & 7);
    const int vncol = (lane >> 4) << 3;

    float* Ab = attn + ((size_t)z * T_ + t0) * S_;
    const bf16* Vhg = g_Vh + (size_t)z * S_ * D_;
    const bf16* Vlg = g_Vl + (size_t)z * S_ * D_;

    if (tid < 128) inv_s[tid] = 1.0f / g_rs[(size_t)z * T_ + t0 + tid];

    auto issueV = [&](int i, int buf) {
        const bf16* sh = Vhg + (size_t)i * 64 * D_;
        const bf16* sl = Vlg + (size_t)i * 64 * D_;
        #pragma unroll
        for (int j2 = 0; j2 < 2; j2++) {
            int j = tid + j2 * 256;
            int r = j >> 3, c = (j & 7) << 3;
            cpa16p(&Vh[buf * VSZ + r * LDQ + c], sh + r * D_ + c);
            cpa16p(&Vl[buf * VSZ + r * LDQ + c], sl + r * D_ + c);
        }
        cp_commit();
    };

    uint32_t aPh[2], aPl[2];
    #pragma unroll
    for (int mt = 0; mt < 2; mt++) {
        int m = wm * 32 + mt * 16 + lrow;
        aPh[mt] = smem_u32(&Ph[m * LDQ + lkof]);
        aPl[mt] = smem_u32(&Pl[m * LDQ + lkof]);
    }

    float acc[2][4][4] = {};
    issueV(0, 0);
    __syncthreads();   // inv_s visible

    for (int it = 0; it < 32; it++) {
        const int buf = it & 1;
        const int k0 = it * 64;
        if (it < 31) { issueV(it + 1, buf ^ 1); cp_wait<1>(); }
        else cp_wait<0>();

        // P tile 128x64: read e, normalize, write final attn, split hi/lo
        #pragma unroll
        for (int i = 0; i < 8; i++) {
            int idx = tid + i * 256;
            int r = idx >> 4, c = (idx & 15) << 2;
            float4 e4 = *(float4*)&Ab[(size_t)r * S_ + k0 + c];
            float inv = inv_s[r];
            e4.x *= inv; e4.y *= inv; e4.z *= inv; e4.w *= inv;
            *(float4*)&Ab[(size_t)r * S_ + k0 + c] = e4;
            uint32_t h01, l01, h23, l23;
            cvt_hilo2(e4.x, e4.y, h01, l01);
            cvt_hilo2(e4.z, e4.w, h23, l23);
            *(uint2*)&Ph[r * LDQ + c] = make_uint2(h01, h23);
            *(uint2*)&Pl[r * LDQ + c] = make_uint2(l01, l23);
        }
        __syncthreads();

        const uint32_t vbase = smem_u32(&Vh[buf * VSZ]);
        const uint32_t lbase = smem_u32(&Vl[buf * VSZ]);

        #pragma unroll
        for (int ks = 0; ks < 4; ks++) {
            const uint32_t kbP = ks * 32;                 // bytes in P (k dim)
            const uint32_t kbV = (uint32_t)(ks * 16 * LDQ * 2);  // 16 s-rows
            uint32_t ah[2][4], al[2][4];
            #pragma unroll
            for (int mt = 0; mt < 2; mt++) {
                ldsm4(ah[mt], aPh[mt] + kbP);
                ldsm4(al[mt], aPl[mt] + kbP);
            }
            #pragma unroll
            for (int ng = 0; ng < 2; ng++) {
                const uint32_t voff = (uint32_t)((vkrow * LDQ + wn * 32 + ng * 16 + vncol) * 2);
                uint32_t bh4[4], bl4[4];
                ldsm4t(bh4, vbase + kbV + voff);
                ldsm4t(bl4, lbase + kbV + voff);
                #pragma unroll
                for (int s = 0; s < 2; s++) {
                    const int nt = ng * 2 + s;
                    uint32_t bh[2] = { bh4[2 * s], bh4[2 * s + 1] };
                    uint32_t bl[2] = { bl4[2 * s], bl4[2 * s + 1] };
                    #pragma unroll
                    for (int mt = 0; mt < 2; mt++) {
                        mma16816(acc[mt][nt], ah[mt], bh);
                        mma16816(acc[mt][nt], al[mt], bh);
                        mma16816(acc[mt][nt], ah[mt], bl);
                    }
                }
            }
        }
        __syncthreads();
    }

    #pragma unroll
    for (int mt = 0; mt < 2; mt++) {
        #pragma unroll
        for (int nt = 0; nt < 4; nt++) {
            int d = wn * 32 + nt * 8 + q2;
            #pragma unroll
            for (int rh = 0; rh < 2; rh++) {
                int mr = t0 + wm * 32 + mt * 16 + rr + rh * 8;
                size_t off = ((size_t)(b * T_ + mr)) * E_ + h * D_ + d;
                uint32_t hh, ll;
                cvt_hilo2(acc[mt][nt][rh * 2], acc[mt][nt][rh * 2 + 1], hh, ll);
                *(uint32_t*)&g_Ch[off] = hh;
                *(uint32_t*)&g_Cl[off] = ll;
            }
        }
    }
}

// ---------------------------------------------------------------------------
extern "C" void kernel_launch(void* const* d_in, const int* in_sizes, int n_in,
                              void* d_out, int out_size)
{
    const float* src = (const float*)d_in[0];
    const float* tgt = (const float*)d_in[1];
    const float* Wq  = (const float*)d_in[2];
    const float* Wk  = (const float*)d_in[3];
    const float* Wv  = (const float*)d_in[4];
    const float* Wo  = (const float*)d_in[5];
    const float* bo  = (const float*)d_in[6];

    float* out  = (float*)d_out;
    float* attn = out + (size_t)BT * E_;

    bf16 *Th, *Tl, *Sh, *Sl, *Wqh, *Wql, *Wkh, *Wkl, *Wvh, *Wvl, *Woh, *Wol;
    bf16 *Qh, *Ql, *Kh, *Kl, *Vh, *Vl, *Ch, *Cl;
    cudaGetSymbolAddress((void**)&Th, g_Th);   cudaGetSymbolAddress((void**)&Tl, g_Tl);
    cudaGetSymbolAddress((void**)&Sh, g_Sh);   cudaGetSymbolAddress((void**)&Sl, g_Sl);
    cudaGetSymbolAddress((void**)&Wqh, g_Wqh); cudaGetSymbolAddress((void**)&Wql, g_Wql);
    cudaGetSymbolAddress((void**)&Wkh, g_Wkh); cudaGetSymbolAddress((void**)&Wkl, g_Wkl);
    cudaGetSymbolAddress((void**)&Wvh, g_Wvh); cudaGetSymbolAddress((void**)&Wvl, g_Wvl);
    cudaGetSymbolAddress((void**)&Woh, g_Woh); cudaGetSymbolAddress((void**)&Wol, g_Wol);
    cudaGetSymbolAddress((void**)&Qh, g_Qh);   cudaGetSymbolAddress((void**)&Ql, g_Ql);
    cudaGetSymbolAddress((void**)&Kh, g_Kh);   cudaGetSymbolAddress((void**)&Kl, g_Kl);
    cudaGetSymbolAddress((void**)&Vh, g_Vh);   cudaGetSymbolAddress((void**)&Vl, g_Vl);
    cudaGetSymbolAddress((void**)&Ch, g_Ch);   cudaGetSymbolAddress((void**)&Cl, g_Cl);

    const int projSmem = 8 * PSZ * (int)sizeof(bf16);                  // 81920
    const int scoSmem  = 6 * QSZ * (int)sizeof(bf16);                  // 110592
    const int ctxSmem  = (2 * 128 * LDQ + 4 * VSZ) * (int)sizeof(bf16); // 73728

    static bool attr_set = false;
    if (!attr_set) {
        cudaFuncSetAttribute(k_proj3, cudaFuncAttributeMaxDynamicSharedMemorySize, projSmem);
        cudaFuncSetAttribute(k_projo, cudaFuncAttributeMaxDynamicSharedMemorySize, projSmem);
        cudaFuncSetAttribute(k_sco, cudaFuncAttributeMaxDynamicSharedMemorySize, scoSmem);
        cudaFuncSetAttribute(k_ctx, cudaFuncAttributeMaxDynamicSharedMemorySize, ctxSmem);
        attr_set = true;
    }

    dim3 blk(256);

    k_cvt<<<(BT * E_ / 4 + 255) / 256, 256>>>(tgt, Th, Tl, BT * E_ / 4);
    k_cvt<<<(BT * E_ / 4 + 255) / 256, 256>>>(src, Sh, Sl, BT * E_ / 4);
    k_cvt<<<(E_ * E_ / 4 + 255) / 256, 256>>>(Wq, Wqh, Wql, E_ * E_ / 4);
    k_cvt<<<(E_ * E_ / 4 + 255) / 256, 256>>>(Wk, Wkh, Wkl, E_ * E_ / 4);
    k_cvt<<<(E_ * E_ / 4 + 255) / 256, 256>>>(Wv, Wvh, Wvl, E_ * E_ / 4);
    k_cvt<<<(E_ * E_ / 4 + 255) / 256, 256>>>(Wo, Woh, Wol, E_ * E_ / 4);

    k_proj3<<<dim3(E_ / 128, BT / 128, 3), blk, projSmem>>>(
        Th, Tl, Sh, Sl, Wqh, Wql, Wkh, Wkl, Wvh, Wvl,
        Qh, Ql, Kh, Kl, Vh, Vl);

    k_sco<<<dim3(T_ / 128, Z_), blk, scoSmem>>>(attn);

    k_ctx<<<dim3(T_ / 128, Z_), blk, ctxSmem>>>(attn);

    k_projo<<<dim3(E_ / 128, BT / 128), blk, projSmem>>>(Ch, Cl, Woh, Wol, out, bo);
}